// round 1
// baseline (speedup 1.0000x reference)
#include <cuda_runtime.h>
#include <math_constants.h>

#define B_ 2
#define L_ 2048
#define D_ 2048
#define H_ 16
#define KV_ 4
#define HD_ 128
#define REP_ (H_ / KV_)

// Scratch (allocation-free rule: device globals)
__device__ float g_q[(size_t)B_ * L_ * D_];            // 32 MB
__device__ float g_k[(size_t)B_ * L_ * KV_ * HD_];     // 8 MB
__device__ float g_v[(size_t)B_ * L_ * KV_ * HD_];     // 8 MB
__device__ float g_ao[(size_t)B_ * L_ * D_];           // 32 MB

// ---------------------------------------------------------------------------
// GEMM: C[M,N] = A[M,Kd] * W[N,Kd]^T   (both row-major, K contiguous: "NT")
// 128x128 block tile, 8x8 microtile, BK=16, 256 threads.
// ---------------------------------------------------------------------------
#define GBM 128
#define GBN 128
#define GBK 16

__global__ __launch_bounds__(256, 2)
void gemm_nt(const float* __restrict__ A, const float* __restrict__ W,
             float* __restrict__ C, int M, int N, int Kd) {
  __shared__ float As[GBK][GBM];
  __shared__ float Bs[GBK][GBN];
  const int bm = blockIdx.y * GBM;
  const int bn = blockIdx.x * GBN;
  const int tid = threadIdx.x;
  const int tr = tid >> 4;   // 0..15
  const int tc = tid & 15;   // 0..15

  float acc[8][8];
#pragma unroll
  for (int i = 0; i < 8; i++)
#pragma unroll
    for (int j = 0; j < 8; j++) acc[i][j] = 0.f;

  for (int k0 = 0; k0 < Kd; k0 += GBK) {
    // cooperative loads: 128 rows x 16 cols = 512 float4 per tile, 2 per thread
#pragma unroll
    for (int i = 0; i < 2; i++) {
      int idx = tid + i * 256;
      int r = idx >> 2;
      int c4 = (idx & 3) * 4;
      float4 va = *(const float4*)(A + (size_t)(bm + r) * Kd + k0 + c4);
      As[c4 + 0][r] = va.x; As[c4 + 1][r] = va.y;
      As[c4 + 2][r] = va.z; As[c4 + 3][r] = va.w;
      float4 vb = *(const float4*)(W + (size_t)(bn + r) * Kd + k0 + c4);
      Bs[c4 + 0][r] = vb.x; Bs[c4 + 1][r] = vb.y;
      Bs[c4 + 2][r] = vb.z; Bs[c4 + 3][r] = vb.w;
    }
    __syncthreads();
#pragma unroll
    for (int kk = 0; kk < GBK; kk++) {
      float a[8], b[8];
      *(float4*)&a[0] = *(const float4*)&As[kk][tr * 8];
      *(float4*)&a[4] = *(const float4*)&As[kk][tr * 8 + 4];
      *(float4*)&b[0] = *(const float4*)&Bs[kk][tc * 8];
      *(float4*)&b[4] = *(const float4*)&Bs[kk][tc * 8 + 4];
#pragma unroll
      for (int i = 0; i < 8; i++)
#pragma unroll
        for (int j = 0; j < 8; j++) acc[i][j] = fmaf(a[i], b[j], acc[i][j]);
    }
    __syncthreads();
  }
#pragma unroll
  for (int i = 0; i < 8; i++) {
    float* cp = C + (size_t)(bm + tr * 8 + i) * N + bn + tc * 8;
    *(float4*)cp       = make_float4(acc[i][0], acc[i][1], acc[i][2], acc[i][3]);
    *(float4*)(cp + 4) = make_float4(acc[i][4], acc[i][5], acc[i][6], acc[i][7]);
  }
}

// ---------------------------------------------------------------------------
// RoPE, interleaved-pair convention, in place on [B*L, nh, HD] tensor.
// ---------------------------------------------------------------------------
__global__ void rope_kernel(float* __restrict__ xp, int nh, int total) {
  int idx = blockIdx.x * blockDim.x + threadIdx.x;
  if (idx >= total) return;
  int i = idx & (HD_ / 2 - 1);     // pair index 0..63
  int t = idx >> 6;
  int h = t % nh;
  int bl = t / nh;
  int pos = bl & (L_ - 1);
  // inv_freq = 10000^(-2i/HD) = exp(-(2i/HD)*ln(10000))
  float inv_freq = expf(-(float)i * (2.0f / HD_) * 9.210340371976184f);
  float ang = (float)pos * inv_freq;
  float s, c;
  sincosf(ang, &s, &c);
  size_t base = ((size_t)bl * nh + h) * HD_ + 2 * i;
  float x1 = xp[base], x2 = xp[base + 1];
  xp[base]     = x1 * c - x2 * s;
  xp[base + 1] = x1 * s + x2 * c;
}

// ---------------------------------------------------------------------------
// Causal flash attention, fp32, online softmax.
// Block: 256 threads = 8 warps; each warp owns 2 query rows; 16 rows/block.
// K/V streamed via 32-key smem tiles; GQA: kv head = h / 4.
// ---------------------------------------------------------------------------
#define FA_TILE 32
#define FA_RPW 2
#define FA_ROWS 16

__global__ __launch_bounds__(256)
void flash_attn(const float* __restrict__ Q, const float* __restrict__ Kg,
                const float* __restrict__ Vg, float* __restrict__ O) {
  __shared__ float Ks[FA_TILE][HD_];
  __shared__ float Vs[FA_TILE][HD_];
  const int b = blockIdx.z;
  const int h = blockIdx.y;
  const int r0 = blockIdx.x * FA_ROWS;
  const int kvh = h / REP_;
  const int warp = threadIdx.x >> 5;
  const int lane = threadIdx.x & 31;
  const int row0 = r0 + warp * FA_RPW;
  const float scale = 0.088388347648318447f;  // 1/sqrt(128)

  float4 q[FA_RPW];
  float m[FA_RPW], l[FA_RPW];
  float4 acc[FA_RPW];
#pragma unroll
  for (int r = 0; r < FA_RPW; r++) {
    float4 t = *(const float4*)(Q + ((size_t)(b * L_ + row0 + r) * H_ + h) * HD_ + lane * 4);
    q[r] = make_float4(t.x * scale, t.y * scale, t.z * scale, t.w * scale);
    m[r] = -CUDART_INF_F;
    l[r] = 0.f;
    acc[r] = make_float4(0.f, 0.f, 0.f, 0.f);
  }

  const int kmax = r0 + FA_ROWS - 1;
  for (int t0 = 0; t0 <= kmax; t0 += FA_TILE) {
    // load 32 keys + values: 32*128 floats = 1024 float4, 4 per thread each
#pragma unroll
    for (int i = 0; i < 4; i++) {
      int f4 = threadIdx.x + i * 256;
      int rr = f4 >> 5;
      int cc = (f4 & 31) * 4;
      size_t g = ((size_t)(b * L_ + t0 + rr) * KV_ + kvh) * HD_ + cc;
      *(float4*)&Ks[rr][cc] = *(const float4*)(Kg + g);
      *(float4*)&Vs[rr][cc] = *(const float4*)(Vg + g);
    }
    __syncthreads();

    const int jend = min(FA_TILE - 1, kmax - t0);
    for (int j = 0; j <= jend; j++) {
      float4 k4 = *(const float4*)&Ks[j][lane * 4];
      float4 v4 = *(const float4*)&Vs[j][lane * 4];
      const int jg = t0 + j;
#pragma unroll
      for (int r = 0; r < FA_RPW; r++) {
        float s = q[r].x * k4.x + q[r].y * k4.y + q[r].z * k4.z + q[r].w * k4.w;
#pragma unroll
        for (int off = 16; off > 0; off >>= 1)
          s += __shfl_xor_sync(0xffffffffu, s, off);
        if (jg > row0 + r) s = -CUDART_INF_F;       // causal mask
        float mn = fmaxf(m[r], s);
        float corr = __expf(m[r] - mn);
        float p = __expf(s - mn);
        l[r] = l[r] * corr + p;
        acc[r].x = acc[r].x * corr + p * v4.x;
        acc[r].y = acc[r].y * corr + p * v4.y;
        acc[r].z = acc[r].z * corr + p * v4.z;
        acc[r].w = acc[r].w * corr + p * v4.w;
        m[r] = mn;
      }
    }
    __syncthreads();
  }

#pragma unroll
  for (int r = 0; r < FA_RPW; r++) {
    float inv = 1.0f / l[r];
    float4 o = make_float4(acc[r].x * inv, acc[r].y * inv, acc[r].z * inv, acc[r].w * inv);
    *(float4*)(O + ((size_t)(b * L_ + row0 + r) * H_ + h) * HD_ + lane * 4) = o;
  }
}

// ---------------------------------------------------------------------------
extern "C" void kernel_launch(void* const* d_in, const int* in_sizes, int n_in,
                              void* d_out, int out_size) {
  (void)in_sizes; (void)n_in; (void)out_size;
  const float* x  = (const float*)d_in[0];
  const float* wq = (const float*)d_in[1];
  const float* wk = (const float*)d_in[2];
  const float* wv = (const float*)d_in[3];
  const float* wo = (const float*)d_in[4];
  float* out = (float*)d_out;

  float *q, *k, *v, *ao;
  cudaGetSymbolAddress((void**)&q, g_q);
  cudaGetSymbolAddress((void**)&k, g_k);
  cudaGetSymbolAddress((void**)&v, g_v);
  cudaGetSymbolAddress((void**)&ao, g_ao);

  const int M = B_ * L_;  // 4096
  dim3 blk(256);

  // Q/K/V projections
  gemm_nt<<<dim3(D_ / GBN, M / GBM), blk>>>(x, wq, q, M, D_, D_);
  gemm_nt<<<dim3((KV_ * HD_) / GBN, M / GBM), blk>>>(x, wk, k, M, KV_ * HD_, D_);
  gemm_nt<<<dim3((KV_ * HD_) / GBN, M / GBM), blk>>>(x, wv, v, M, KV_ * HD_, D_);

  // RoPE on q and k
  int nq = B_ * L_ * H_ * (HD_ / 2);
  rope_kernel<<<nq / 256, 256>>>(q, H_, nq);
  int nk = B_ * L_ * KV_ * (HD_ / 2);
  rope_kernel<<<nk / 256, 256>>>(k, KV_, nk);

  // causal attention
  flash_attn<<<dim3(L_ / FA_ROWS, H_, B_), 256>>>(q, k, v, ao);

  // output projection -> d_out
  gemm_nt<<<dim3(D_ / GBN, M / GBM), blk>>>(ao, wo, out, M, D_, D_);
}

// round 2
// speedup vs baseline: 2.1523x; 2.1523x over previous
#include <cuda_runtime.h>
#include <math_constants.h>

#define B_ 2
#define L_ 2048
#define D_ 2048
#define H_ 16
#define KV_ 4
#define HD_ 128
#define REP_ (H_ / KV_)

// Scratch (allocation-free rule: device globals)
__device__ float g_q[(size_t)B_ * L_ * D_];            // 32 MB
__device__ float g_k[(size_t)B_ * L_ * KV_ * HD_];     // 8 MB
__device__ float g_v[(size_t)B_ * L_ * KV_ * HD_];     // 8 MB
__device__ float g_ao[(size_t)B_ * L_ * D_];           // 32 MB

// ---------------------------------------------------------------------------
// TF32 tensor-core GEMM: C[M,N] = A[M,Kd] * W[N,Kd]^T  (row-major, NT)
// 128x128 block tile, BK=16, 256 threads (8 warps, 2x4), warp tile 64x32.
// mma.sync.aligned.m16n8k8.row.col.f32.tf32.tf32.f32, double-buffered smem.
// ---------------------------------------------------------------------------
#define BM 128
#define BN 128
#define BKt 16
#define PAD 8
#define LDS_ (BM + PAD)   // 136: 136 mod 32 == 8 -> conflict-free frags

__device__ __forceinline__ unsigned f2tf32(float x) {
  unsigned r;
  asm("cvt.rna.tf32.f32 %0, %1;" : "=r"(r) : "f"(x));
  return r;
}

__device__ __forceinline__ void mma_tf32(float c[4], const unsigned a[4],
                                         const unsigned b[2]) {
  asm volatile(
      "mma.sync.aligned.m16n8k8.row.col.f32.tf32.tf32.f32 "
      "{%0,%1,%2,%3}, {%4,%5,%6,%7}, {%8,%9}, {%0,%1,%2,%3};"
      : "+f"(c[0]), "+f"(c[1]), "+f"(c[2]), "+f"(c[3])
      : "r"(a[0]), "r"(a[1]), "r"(a[2]), "r"(a[3]), "r"(b[0]), "r"(b[1]));
}

__global__ __launch_bounds__(256, 2)
void gemm_tf32(const float* __restrict__ A, const float* __restrict__ W,
               float* __restrict__ C, int M, int N, int Kd) {
  __shared__ unsigned As[2][BKt][LDS_];
  __shared__ unsigned Bs[2][BKt][LDS_];
  const int bm = blockIdx.y * BM;
  const int bn = blockIdx.x * BN;
  const int tid = threadIdx.x;
  const int warp = tid >> 5;
  const int lane = tid & 31;
  const int g = lane >> 2;      // 0..7
  const int tig = lane & 3;     // 0..3
  const int m0 = (warp >> 2) * 64;
  const int n0 = (warp & 3) * 32;

  float acc[4][4][4];
#pragma unroll
  for (int i = 0; i < 4; i++)
#pragma unroll
    for (int j = 0; j < 4; j++)
#pragma unroll
      for (int q = 0; q < 4; q++) acc[i][j][q] = 0.f;

  // load mapping: 512 float4 per tile per matrix, 2 per thread
  int r0_ = (tid + 0) >> 2, c0_ = ((tid + 0) & 3) * 4;
  int r1_ = (tid + 256) >> 2, c1_ = ((tid + 256) & 3) * 4;

  float4 stA0, stA1, stB0, stB1;
  const float* Ab = A + (size_t)bm * Kd;
  const float* Wb = W + (size_t)bn * Kd;

#define GLOAD(k0)                                                        \
  do {                                                                   \
    stA0 = *(const float4*)(Ab + (size_t)r0_ * Kd + (k0) + c0_);         \
    stA1 = *(const float4*)(Ab + (size_t)r1_ * Kd + (k0) + c1_);         \
    stB0 = *(const float4*)(Wb + (size_t)r0_ * Kd + (k0) + c0_);         \
    stB1 = *(const float4*)(Wb + (size_t)r1_ * Kd + (k0) + c1_);         \
  } while (0)

#define SSTORE(buf)                                                      \
  do {                                                                   \
    As[buf][c0_ + 0][r0_] = f2tf32(stA0.x);                              \
    As[buf][c0_ + 1][r0_] = f2tf32(stA0.y);                              \
    As[buf][c0_ + 2][r0_] = f2tf32(stA0.z);                              \
    As[buf][c0_ + 3][r0_] = f2tf32(stA0.w);                              \
    As[buf][c1_ + 0][r1_] = f2tf32(stA1.x);                              \
    As[buf][c1_ + 1][r1_] = f2tf32(stA1.y);                              \
    As[buf][c1_ + 2][r1_] = f2tf32(stA1.z);                              \
    As[buf][c1_ + 3][r1_] = f2tf32(stA1.w);                              \
    Bs[buf][c0_ + 0][r0_] = f2tf32(stB0.x);                              \
    Bs[buf][c0_ + 1][r0_] = f2tf32(stB0.y);                              \
    Bs[buf][c0_ + 2][r0_] = f2tf32(stB0.z);                              \
    Bs[buf][c0_ + 3][r0_] = f2tf32(stB0.w);                              \
    Bs[buf][c1_ + 0][r1_] = f2tf32(stB1.x);                              \
    Bs[buf][c1_ + 1][r1_] = f2tf32(stB1.y);                              \
    Bs[buf][c1_ + 2][r1_] = f2tf32(stB1.z);                              \
    Bs[buf][c1_ + 3][r1_] = f2tf32(stB1.w);                              \
  } while (0)

  GLOAD(0);
  SSTORE(0);
  __syncthreads();

  const int ntiles = Kd / BKt;
  for (int t = 0; t < ntiles; t++) {
    const int buf = t & 1;
    if (t + 1 < ntiles) GLOAD((t + 1) * BKt);

#pragma unroll
    for (int ks = 0; ks < 2; ks++) {
      const int kb = ks * 8;
      unsigned a[4][4], b[4][2];
#pragma unroll
      for (int i = 0; i < 4; i++) {
        const int mb = m0 + i * 16 + g;
        a[i][0] = As[buf][kb + tig][mb];
        a[i][1] = As[buf][kb + tig][mb + 8];
        a[i][2] = As[buf][kb + tig + 4][mb];
        a[i][3] = As[buf][kb + tig + 4][mb + 8];
      }
#pragma unroll
      for (int j = 0; j < 4; j++) {
        const int nb = n0 + j * 8 + g;
        b[j][0] = Bs[buf][kb + tig][nb];
        b[j][1] = Bs[buf][kb + tig + 4][nb];
      }
#pragma unroll
      for (int i = 0; i < 4; i++)
#pragma unroll
        for (int j = 0; j < 4; j++) mma_tf32(acc[i][j], a[i], b[j]);
    }

    if (t + 1 < ntiles) SSTORE(buf ^ 1);
    __syncthreads();
  }

  // epilogue: c0,c1 -> (row g, cols tig*2,tig*2+1); c2,c3 -> row g+8
#pragma unroll
  for (int i = 0; i < 4; i++) {
#pragma unroll
    for (int j = 0; j < 4; j++) {
      const size_t row1 = (size_t)(bm + m0 + i * 16 + g);
      const int col = bn + n0 + j * 8 + tig * 2;
      *(float2*)(C + row1 * N + col) = make_float2(acc[i][j][0], acc[i][j][1]);
      *(float2*)(C + (row1 + 8) * N + col) = make_float2(acc[i][j][2], acc[i][j][3]);
    }
  }
}

// ---------------------------------------------------------------------------
// RoPE, interleaved-pair convention, in place on [B*L, nh, HD] tensor.
// ---------------------------------------------------------------------------
__global__ void rope_kernel(float* __restrict__ xp, int nh, int total) {
  int idx = blockIdx.x * blockDim.x + threadIdx.x;
  if (idx >= total) return;
  int i = idx & (HD_ / 2 - 1);
  int t = idx >> 6;
  int h = t % nh;
  int bl = t / nh;
  int pos = bl & (L_ - 1);
  float inv_freq = expf(-(float)i * (2.0f / HD_) * 9.210340371976184f);
  float ang = (float)pos * inv_freq;
  float s, c;
  sincosf(ang, &s, &c);
  size_t base = ((size_t)bl * nh + h) * HD_ + 2 * i;
  float x1 = xp[base], x2 = xp[base + 1];
  xp[base]     = x1 * c - x2 * s;
  xp[base + 1] = x1 * s + x2 * c;
}

// ---------------------------------------------------------------------------
// Causal flash attention, fp32, online softmax (unchanged from round 1).
// ---------------------------------------------------------------------------
#define FA_TILE 32
#define FA_RPW 2
#define FA_ROWS 16

__global__ __launch_bounds__(256)
void flash_attn(const float* __restrict__ Q, const float* __restrict__ Kg,
                const float* __restrict__ Vg, float* __restrict__ O) {
  __shared__ float Ks[FA_TILE][HD_];
  __shared__ float Vs[FA_TILE][HD_];
  const int b = blockIdx.z;
  const int h = blockIdx.y;
  const int r0 = blockIdx.x * FA_ROWS;
  const int kvh = h / REP_;
  const int warp = threadIdx.x >> 5;
  const int lane = threadIdx.x & 31;
  const int row0 = r0 + warp * FA_RPW;
  const float scale = 0.088388347648318447f;

  float4 q[FA_RPW];
  float m[FA_RPW], l[FA_RPW];
  float4 acc[FA_RPW];
#pragma unroll
  for (int r = 0; r < FA_RPW; r++) {
    float4 t = *(const float4*)(Q + ((size_t)(b * L_ + row0 + r) * H_ + h) * HD_ + lane * 4);
    q[r] = make_float4(t.x * scale, t.y * scale, t.z * scale, t.w * scale);
    m[r] = -CUDART_INF_F;
    l[r] = 0.f;
    acc[r] = make_float4(0.f, 0.f, 0.f, 0.f);
  }

  const int kmax = r0 + FA_ROWS - 1;
  for (int t0 = 0; t0 <= kmax; t0 += FA_TILE) {
#pragma unroll
    for (int i = 0; i < 4; i++) {
      int f4 = threadIdx.x + i * 256;
      int rr = f4 >> 5;
      int cc = (f4 & 31) * 4;
      size_t gidx = ((size_t)(b * L_ + t0 + rr) * KV_ + kvh) * HD_ + cc;
      *(float4*)&Ks[rr][cc] = *(const float4*)(Kg + gidx);
      *(float4*)&Vs[rr][cc] = *(const float4*)(Vg + gidx);
    }
    __syncthreads();

    const int jend = min(FA_TILE - 1, kmax - t0);
    for (int j = 0; j <= jend; j++) {
      float4 k4 = *(const float4*)&Ks[j][lane * 4];
      float4 v4 = *(const float4*)&Vs[j][lane * 4];
      const int jg = t0 + j;
#pragma unroll
      for (int r = 0; r < FA_RPW; r++) {
        float s = q[r].x * k4.x + q[r].y * k4.y + q[r].z * k4.z + q[r].w * k4.w;
#pragma unroll
        for (int off = 16; off > 0; off >>= 1)
          s += __shfl_xor_sync(0xffffffffu, s, off);
        if (jg > row0 + r) s = -CUDART_INF_F;
        float mn = fmaxf(m[r], s);
        float corr = __expf(m[r] - mn);
        float p = __expf(s - mn);
        l[r] = l[r] * corr + p;
        acc[r].x = acc[r].x * corr + p * v4.x;
        acc[r].y = acc[r].y * corr + p * v4.y;
        acc[r].z = acc[r].z * corr + p * v4.z;
        acc[r].w = acc[r].w * corr + p * v4.w;
        m[r] = mn;
      }
    }
    __syncthreads();
  }

#pragma unroll
  for (int r = 0; r < FA_RPW; r++) {
    float inv = 1.0f / l[r];
    float4 o = make_float4(acc[r].x * inv, acc[r].y * inv, acc[r].z * inv, acc[r].w * inv);
    *(float4*)(O + ((size_t)(b * L_ + row0 + r) * H_ + h) * HD_ + lane * 4) = o;
  }
}

// ---------------------------------------------------------------------------
extern "C" void kernel_launch(void* const* d_in, const int* in_sizes, int n_in,
                              void* d_out, int out_size) {
  (void)in_sizes; (void)n_in; (void)out_size;
  const float* x  = (const float*)d_in[0];
  const float* wq = (const float*)d_in[1];
  const float* wk = (const float*)d_in[2];
  const float* wv = (const float*)d_in[3];
  const float* wo = (const float*)d_in[4];
  float* out = (float*)d_out;

  float *q, *k, *v, *ao;
  cudaGetSymbolAddress((void**)&q, g_q);
  cudaGetSymbolAddress((void**)&k, g_k);
  cudaGetSymbolAddress((void**)&v, g_v);
  cudaGetSymbolAddress((void**)&ao, g_ao);

  const int M = B_ * L_;  // 4096
  dim3 blk(256);

  // Q/K/V projections (tf32 tensor cores)
  gemm_tf32<<<dim3(D_ / BN, M / BM), blk>>>(x, wq, q, M, D_, D_);
  gemm_tf32<<<dim3((KV_ * HD_) / BN, M / BM), blk>>>(x, wk, k, M, KV_ * HD_, D_);
  gemm_tf32<<<dim3((KV_ * HD_) / BN, M / BM), blk>>>(x, wv, v, M, KV_ * HD_, D_);

  // RoPE on q and k
  int nq = B_ * L_ * H_ * (HD_ / 2);
  rope_kernel<<<nq / 256, 256>>>(q, H_, nq);
  int nk = B_ * L_ * KV_ * (HD_ / 2);
  rope_kernel<<<nk / 256, 256>>>(k, KV_, nk);

  // causal attention
  flash_attn<<<dim3(L_ / FA_ROWS, H_, B_), 256>>>(q, k, v, ao);

  // output projection -> d_out
  gemm_tf32<<<dim3(D_ / BN, M / BM), blk>>>(ao, wo, out, M, D_, D_);
}

// round 3
// speedup vs baseline: 6.1436x; 2.8544x over previous
#include <cuda_runtime.h>
#include <math_constants.h>

#define B_ 2
#define L_ 2048
#define D_ 2048
#define H_ 16
#define KV_ 4
#define HD_ 128
#define REP_ (H_ / KV_)

// Scratch (allocation-free rule: device globals)
__device__ float g_q[(size_t)B_ * L_ * D_];            // 32 MB
__device__ float g_k[(size_t)B_ * L_ * KV_ * HD_];     // 8 MB
__device__ float g_v[(size_t)B_ * L_ * KV_ * HD_];     // 8 MB
__device__ float g_ao[(size_t)B_ * L_ * D_];           // 32 MB

__device__ __forceinline__ unsigned f2tf32(float x) {
  unsigned r;
  asm("cvt.rna.tf32.f32 %0, %1;" : "=r"(r) : "f"(x));
  return r;
}

__device__ __forceinline__ void mma_tf32(float c[4], const unsigned a[4],
                                         const unsigned b[2]) {
  asm volatile(
      "mma.sync.aligned.m16n8k8.row.col.f32.tf32.tf32.f32 "
      "{%0,%1,%2,%3}, {%4,%5,%6,%7}, {%8,%9}, {%0,%1,%2,%3};"
      : "+f"(c[0]), "+f"(c[1]), "+f"(c[2]), "+f"(c[3])
      : "r"(a[0]), "r"(a[1]), "r"(a[2]), "r"(a[3]), "r"(b[0]), "r"(b[1]));
}

// ---------------------------------------------------------------------------
// TF32 tensor-core GEMM: C[M,N] = A[M,Kd] * W[N,Kd]^T  (row-major, NT)
// (unchanged from round 2)
// ---------------------------------------------------------------------------
#define BM 128
#define BN 128
#define BKt 16
#define PAD 8
#define LDS_ (BM + PAD)

__global__ __launch_bounds__(256, 2)
void gemm_tf32(const float* __restrict__ A, const float* __restrict__ W,
               float* __restrict__ C, int M, int N, int Kd) {
  __shared__ unsigned As[2][BKt][LDS_];
  __shared__ unsigned Bs[2][BKt][LDS_];
  const int bm = blockIdx.y * BM;
  const int bn = blockIdx.x * BN;
  const int tid = threadIdx.x;
  const int warp = tid >> 5;
  const int lane = tid & 31;
  const int g = lane >> 2;
  const int tig = lane & 3;
  const int m0 = (warp >> 2) * 64;
  const int n0 = (warp & 3) * 32;

  float acc[4][4][4];
#pragma unroll
  for (int i = 0; i < 4; i++)
#pragma unroll
    for (int j = 0; j < 4; j++)
#pragma unroll
      for (int q = 0; q < 4; q++) acc[i][j][q] = 0.f;

  int r0_ = (tid + 0) >> 2, c0_ = ((tid + 0) & 3) * 4;
  int r1_ = (tid + 256) >> 2, c1_ = ((tid + 256) & 3) * 4;

  float4 stA0, stA1, stB0, stB1;
  const float* Ab = A + (size_t)bm * Kd;
  const float* Wb = W + (size_t)bn * Kd;

#define GLOAD(k0)                                                        \
  do {                                                                   \
    stA0 = *(const float4*)(Ab + (size_t)r0_ * Kd + (k0) + c0_);         \
    stA1 = *(const float4*)(Ab + (size_t)r1_ * Kd + (k0) + c1_);         \
    stB0 = *(const float4*)(Wb + (size_t)r0_ * Kd + (k0) + c0_);         \
    stB1 = *(const float4*)(Wb + (size_t)r1_ * Kd + (k0) + c1_);         \
  } while (0)

#define SSTORE(buf)                                                      \
  do {                                                                   \
    As[buf][c0_ + 0][r0_] = f2tf32(stA0.x);                              \
    As[buf][c0_ + 1][r0_] = f2tf32(stA0.y);                              \
    As[buf][c0_ + 2][r0_] = f2tf32(stA0.z);                              \
    As[buf][c0_ + 3][r0_] = f2tf32(stA0.w);                              \
    As[buf][c1_ + 0][r1_] = f2tf32(stA1.x);                              \
    As[buf][c1_ + 1][r1_] = f2tf32(stA1.y);                              \
    As[buf][c1_ + 2][r1_] = f2tf32(stA1.z);                              \
    As[buf][c1_ + 3][r1_] = f2tf32(stA1.w);                              \
    Bs[buf][c0_ + 0][r0_] = f2tf32(stB0.x);                              \
    Bs[buf][c0_ + 1][r0_] = f2tf32(stB0.y);                              \
    Bs[buf][c0_ + 2][r0_] = f2tf32(stB0.z);                              \
    Bs[buf][c0_ + 3][r0_] = f2tf32(stB0.w);                              \
    Bs[buf][c1_ + 0][r1_] = f2tf32(stB1.x);                              \
    Bs[buf][c1_ + 1][r1_] = f2tf32(stB1.y);                              \
    Bs[buf][c1_ + 2][r1_] = f2tf32(stB1.z);                              \
    Bs[buf][c1_ + 3][r1_] = f2tf32(stB1.w);                              \
  } while (0)

  GLOAD(0);
  SSTORE(0);
  __syncthreads();

  const int ntiles = Kd / BKt;
  for (int t = 0; t < ntiles; t++) {
    const int buf = t & 1;
    if (t + 1 < ntiles) GLOAD((t + 1) * BKt);

#pragma unroll
    for (int ks = 0; ks < 2; ks++) {
      const int kb = ks * 8;
      unsigned a[4][4], b[4][2];
#pragma unroll
      for (int i = 0; i < 4; i++) {
        const int mb = m0 + i * 16 + g;
        a[i][0] = As[buf][kb + tig][mb];
        a[i][1] = As[buf][kb + tig][mb + 8];
        a[i][2] = As[buf][kb + tig + 4][mb];
        a[i][3] = As[buf][kb + tig + 4][mb + 8];
      }
#pragma unroll
      for (int j = 0; j < 4; j++) {
        const int nb = n0 + j * 8 + g;
        b[j][0] = Bs[buf][kb + tig][nb];
        b[j][1] = Bs[buf][kb + tig + 4][nb];
      }
#pragma unroll
      for (int i = 0; i < 4; i++)
#pragma unroll
        for (int j = 0; j < 4; j++) mma_tf32(acc[i][j], a[i], b[j]);
    }

    if (t + 1 < ntiles) SSTORE(buf ^ 1);
    __syncthreads();
  }

#pragma unroll
  for (int i = 0; i < 4; i++) {
#pragma unroll
    for (int j = 0; j < 4; j++) {
      const size_t row1 = (size_t)(bm + m0 + i * 16 + g);
      const int col = bn + n0 + j * 8 + tig * 2;
      *(float2*)(C + row1 * N + col) = make_float2(acc[i][j][0], acc[i][j][1]);
      *(float2*)(C + (row1 + 8) * N + col) = make_float2(acc[i][j][2], acc[i][j][3]);
    }
  }
}

// ---------------------------------------------------------------------------
// RoPE (unchanged)
// ---------------------------------------------------------------------------
__global__ void rope_kernel(float* __restrict__ xp, int nh, int total) {
  int idx = blockIdx.x * blockDim.x + threadIdx.x;
  if (idx >= total) return;
  int i = idx & (HD_ / 2 - 1);
  int t = idx >> 6;
  int h = t % nh;
  int bl = t / nh;
  int pos = bl & (L_ - 1);
  float inv_freq = expf(-(float)i * (2.0f / HD_) * 9.210340371976184f);
  float ang = (float)pos * inv_freq;
  float s, c;
  sincosf(ang, &s, &c);
  size_t base = ((size_t)bl * nh + h) * HD_ + 2 * i;
  float x1 = xp[base], x2 = xp[base + 1];
  xp[base]     = x1 * c - x2 * s;
  xp[base + 1] = x1 * s + x2 * c;
}

// ---------------------------------------------------------------------------
// Tensor-core causal flash attention (tf32 mma, online softmax).
// CTA: 4 warps x 16 q-rows = 64 rows of one (b,h). Key tiles of 32.
// K/V smem in natural [key][d] layout (frag pattern is conflict-free, pad 132).
// P re-shaped C-frag -> A-frag via per-warp smem buffer.
// ---------------------------------------------------------------------------
#define AT_TK 32
#define AT_WQ 16
#define AT_WARPS 4
#define AT_QB (AT_WQ * AT_WARPS)   // 64
#define KV_LD 132
#define P_LD 36

__global__ __launch_bounds__(128, 2)
void flash_attn_tc(const float* __restrict__ Q, const float* __restrict__ Kg,
                   const float* __restrict__ Vg, float* __restrict__ O) {
  __shared__ unsigned Ks[AT_TK][KV_LD];
  __shared__ unsigned Vs[AT_TK][KV_LD];
  __shared__ unsigned Ps[AT_WARPS][AT_WQ][P_LD];

  const int b = blockIdx.z;
  const int h = blockIdx.y;
  const int r0 = blockIdx.x * AT_QB;
  const int kvh = h / REP_;
  const int warp = threadIdx.x >> 5;
  const int lane = threadIdx.x & 31;
  const int g = lane >> 2;    // 0..7
  const int tig = lane & 3;   // 0..3
  const int row0 = r0 + warp * AT_WQ;
  const float scale = 0.088388347648318447f;  // 1/sqrt(128)

  // persistent Q fragments (scale folded in):  qa[kstep][4]
  unsigned qa[16][4];
  {
    const float* Qb = Q + ((size_t)(b * L_ + row0) * H_ + h) * HD_;
    // consecutive q rows stride H_*HD_ = D_
#pragma unroll
    for (int ks = 0; ks < 16; ks++) {
      const int k0 = ks * 8;
      qa[ks][0] = f2tf32(Qb[(size_t)g * D_ + k0 + tig] * scale);
      qa[ks][1] = f2tf32(Qb[(size_t)(g + 8) * D_ + k0 + tig] * scale);
      qa[ks][2] = f2tf32(Qb[(size_t)g * D_ + k0 + tig + 4] * scale);
      qa[ks][3] = f2tf32(Qb[(size_t)(g + 8) * D_ + k0 + tig + 4] * scale);
    }
  }

  float m0v = -CUDART_INF_F, m1v = -CUDART_INF_F;
  float l0 = 0.f, l1 = 0.f;
  float oa[16][4];
#pragma unroll
  for (int j = 0; j < 16; j++)
#pragma unroll
    for (int q = 0; q < 4; q++) oa[j][q] = 0.f;

  const int tmax = row0 + AT_WQ - 1;     // last key this warp needs
  const int t_end = r0 + AT_QB - 1;      // CTA loop bound

  for (int t0 = 0; t0 <= t_end; t0 += AT_TK) {
    // ---- stage K/V tile (fp32 -> tf32) ----
#pragma unroll
    for (int i = 0; i < 8; i++) {
      int idx = threadIdx.x + i * 128;
      int row = idx >> 5;
      int c4 = (idx & 31) * 4;
      size_t gp = ((size_t)(b * L_ + t0 + row) * KV_ + kvh) * HD_ + c4;
      float4 k4 = *(const float4*)(Kg + gp);
      *(uint4*)&Ks[row][c4] =
          make_uint4(f2tf32(k4.x), f2tf32(k4.y), f2tf32(k4.z), f2tf32(k4.w));
      float4 v4 = *(const float4*)(Vg + gp);
      *(uint4*)&Vs[row][c4] =
          make_uint4(f2tf32(v4.x), f2tf32(v4.y), f2tf32(v4.z), f2tf32(v4.w));
    }
    __syncthreads();

    if (t0 <= tmax) {                    // skip fully-masked tiles for this warp
      // ---- S = Q K^T  (4 n-tiles of 8 keys) ----
      float sf[4][4];
#pragma unroll
      for (int j = 0; j < 4; j++)
#pragma unroll
        for (int q = 0; q < 4; q++) sf[j][q] = 0.f;

#pragma unroll
      for (int ks = 0; ks < 16; ks++) {
        const int kb = ks * 8;
        unsigned bk[4][2];
#pragma unroll
        for (int j = 0; j < 4; j++) {
          bk[j][0] = Ks[j * 8 + g][kb + tig];
          bk[j][1] = Ks[j * 8 + g][kb + tig + 4];
        }
#pragma unroll
        for (int j = 0; j < 4; j++) mma_tf32(sf[j], qa[ks], bk[j]);
      }

      // ---- causal mask (only on partially-masked tiles) ----
      if (t0 + AT_TK - 1 > row0) {
#pragma unroll
        for (int j = 0; j < 4; j++) {
          const int col = t0 + j * 8 + 2 * tig;
          if (col > row0 + g) sf[j][0] = -CUDART_INF_F;
          if (col + 1 > row0 + g) sf[j][1] = -CUDART_INF_F;
          if (col > row0 + g + 8) sf[j][2] = -CUDART_INF_F;
          if (col + 1 > row0 + g + 8) sf[j][3] = -CUDART_INF_F;
        }
      }

      // ---- online softmax on fragments ----
      float tm0 = sf[0][0], tm1 = sf[0][2];
#pragma unroll
      for (int j = 0; j < 4; j++) {
        tm0 = fmaxf(tm0, fmaxf(sf[j][0], sf[j][1]));
        tm1 = fmaxf(tm1, fmaxf(sf[j][2], sf[j][3]));
      }
      tm0 = fmaxf(tm0, __shfl_xor_sync(0xffffffffu, tm0, 1));
      tm0 = fmaxf(tm0, __shfl_xor_sync(0xffffffffu, tm0, 2));
      tm1 = fmaxf(tm1, __shfl_xor_sync(0xffffffffu, tm1, 1));
      tm1 = fmaxf(tm1, __shfl_xor_sync(0xffffffffu, tm1, 2));

      const float mn0 = fmaxf(m0v, tm0);
      const float mn1 = fmaxf(m1v, tm1);
      const float cr0 = __expf(m0v - mn0);
      const float cr1 = __expf(m1v - mn1);

      float ps0 = 0.f, ps1 = 0.f;
#pragma unroll
      for (int j = 0; j < 4; j++) {
        sf[j][0] = __expf(sf[j][0] - mn0);
        sf[j][1] = __expf(sf[j][1] - mn0);
        sf[j][2] = __expf(sf[j][2] - mn1);
        sf[j][3] = __expf(sf[j][3] - mn1);
        ps0 += sf[j][0] + sf[j][1];
        ps1 += sf[j][2] + sf[j][3];
      }
      ps0 += __shfl_xor_sync(0xffffffffu, ps0, 1);
      ps0 += __shfl_xor_sync(0xffffffffu, ps0, 2);
      ps1 += __shfl_xor_sync(0xffffffffu, ps1, 1);
      ps1 += __shfl_xor_sync(0xffffffffu, ps1, 2);

      l0 = l0 * cr0 + ps0;
      l1 = l1 * cr1 + ps1;
      m0v = mn0;
      m1v = mn1;

#pragma unroll
      for (int j2 = 0; j2 < 16; j2++) {
        oa[j2][0] *= cr0; oa[j2][1] *= cr0;
        oa[j2][2] *= cr1; oa[j2][3] *= cr1;
      }

      // ---- P to per-warp smem (C-frag -> A-frag reshape) ----
#pragma unroll
      for (int j = 0; j < 4; j++) {
        *(uint2*)&Ps[warp][g][j * 8 + 2 * tig] =
            make_uint2(f2tf32(sf[j][0]), f2tf32(sf[j][1]));
        *(uint2*)&Ps[warp][g + 8][j * 8 + 2 * tig] =
            make_uint2(f2tf32(sf[j][2]), f2tf32(sf[j][3]));
      }
      __syncwarp();

      // ---- O += P V  (4 k-steps x 16 d-tiles) ----
#pragma unroll
      for (int kb4 = 0; kb4 < 4; kb4++) {
        const int kb = kb4 * 8;
        unsigned pa[4];
        pa[0] = Ps[warp][g][kb + tig];
        pa[1] = Ps[warp][g + 8][kb + tig];
        pa[2] = Ps[warp][g][kb + tig + 4];
        pa[3] = Ps[warp][g + 8][kb + tig + 4];
#pragma unroll
        for (int j2 = 0; j2 < 16; j2++) {
          unsigned bv[2];
          bv[0] = Vs[kb + tig][j2 * 8 + g];
          bv[1] = Vs[kb + tig + 4][j2 * 8 + g];
          mma_tf32(oa[j2], pa, bv);
        }
      }
    }
    __syncthreads();
  }

  // ---- epilogue ----
  const float inv0 = 1.0f / l0;
  const float inv1 = 1.0f / l1;
  float* Ob = O + ((size_t)(b * L_ + row0) * H_ + h) * HD_;
#pragma unroll
  for (int j2 = 0; j2 < 16; j2++) {
    const int col = j2 * 8 + 2 * tig;
    *(float2*)(Ob + (size_t)g * D_ + col) =
        make_float2(oa[j2][0] * inv0, oa[j2][1] * inv0);
    *(float2*)(Ob + (size_t)(g + 8) * D_ + col) =
        make_float2(oa[j2][2] * inv1, oa[j2][3] * inv1);
  }
}

// ---------------------------------------------------------------------------
extern "C" void kernel_launch(void* const* d_in, const int* in_sizes, int n_in,
                              void* d_out, int out_size) {
  (void)in_sizes; (void)n_in; (void)out_size;
  const float* x  = (const float*)d_in[0];
  const float* wq = (const float*)d_in[1];
  const float* wk = (const float*)d_in[2];
  const float* wv = (const float*)d_in[3];
  const float* wo = (const float*)d_in[4];
  float* out = (float*)d_out;

  float *q, *k, *v, *ao;
  cudaGetSymbolAddress((void**)&q, g_q);
  cudaGetSymbolAddress((void**)&k, g_k);
  cudaGetSymbolAddress((void**)&v, g_v);
  cudaGetSymbolAddress((void**)&ao, g_ao);

  const int M = B_ * L_;  // 4096
  dim3 blk(256);

  // Q/K/V projections (tf32 tensor cores)
  gemm_tf32<<<dim3(D_ / BN, M / BM), blk>>>(x, wq, q, M, D_, D_);
  gemm_tf32<<<dim3((KV_ * HD_) / BN, M / BM), blk>>>(x, wk, k, M, KV_ * HD_, D_);
  gemm_tf32<<<dim3((KV_ * HD_) / BN, M / BM), blk>>>(x, wv, v, M, KV_ * HD_, D_);

  // RoPE on q and k
  int nq = B_ * L_ * H_ * (HD_ / 2);
  rope_kernel<<<nq / 256, 256>>>(q, H_, nq);
  int nk = B_ * L_ * KV_ * (HD_ / 2);
  rope_kernel<<<nk / 256, 256>>>(k, KV_, nk);

  // causal attention (tensor cores)
  flash_attn_tc<<<dim3(L_ / AT_QB, H_, B_), 128>>>(q, k, v, ao);

  // output projection -> d_out
  gemm_tf32<<<dim3(D_ / BN, M / BM), blk>>>(ao, wo, out, M, D_, D_);
}

// round 5
// speedup vs baseline: 10.9660x; 1.7849x over previous
#include <cuda_runtime.h>
#include <cuda_fp16.h>
#include <math_constants.h>
#include <cstdint>

#define B_ 2
#define L_ 2048
#define D_ 2048
#define H_ 16
#define KV_ 4
#define HD_ 128
#define REP_ (H_ / KV_)

// Scratch (allocation-free rule: device globals)
__device__ float g_q[(size_t)B_ * L_ * D_];             // 32 MB
__device__ float g_k[(size_t)B_ * L_ * KV_ * HD_];      // 8 MB
__device__ float g_v[(size_t)B_ * L_ * KV_ * HD_];      // 8 MB
__device__ __half g_xh[(size_t)B_ * L_ * D_];           // 16 MB
__device__ __half g_wqh[(size_t)D_ * D_];               // 8 MB
__device__ __half g_wkh[(size_t)KV_ * HD_ * D_];        // 2 MB
__device__ __half g_wvh[(size_t)KV_ * HD_ * D_];        // 2 MB
__device__ __half g_woh[(size_t)D_ * D_];               // 8 MB
__device__ __half g_aoh[(size_t)B_ * L_ * D_];          // 16 MB

// ---------------------------------------------------------------------------
// helpers
// ---------------------------------------------------------------------------
__device__ __forceinline__ unsigned f2tf32(float x) {
  unsigned r;
  asm("cvt.rna.tf32.f32 %0, %1;" : "=r"(r) : "f"(x));
  return r;
}

__device__ __forceinline__ void mma_tf32(float c[4], const unsigned a[4],
                                         const unsigned b[2]) {
  asm volatile(
      "mma.sync.aligned.m16n8k8.row.col.f32.tf32.tf32.f32 "
      "{%0,%1,%2,%3}, {%4,%5,%6,%7}, {%8,%9}, {%0,%1,%2,%3};"
      : "+f"(c[0]), "+f"(c[1]), "+f"(c[2]), "+f"(c[3])
      : "r"(a[0]), "r"(a[1]), "r"(a[2]), "r"(a[3]), "r"(b[0]), "r"(b[1]));
}

__device__ __forceinline__ void mma_f16(float c[4], const unsigned a[4],
                                        const unsigned b[2]) {
  asm volatile(
      "mma.sync.aligned.m16n8k16.row.col.f32.f16.f16.f32 "
      "{%0,%1,%2,%3}, {%4,%5,%6,%7}, {%8,%9}, {%0,%1,%2,%3};"
      : "+f"(c[0]), "+f"(c[1]), "+f"(c[2]), "+f"(c[3])
      : "r"(a[0]), "r"(a[1]), "r"(a[2]), "r"(a[3]), "r"(b[0]), "r"(b[1]));
}

__device__ __forceinline__ void ldmx4(unsigned r[4], uint32_t addr) {
  asm volatile(
      "ldmatrix.sync.aligned.m8n8.x4.shared.b16 {%0,%1,%2,%3}, [%4];"
      : "=r"(r[0]), "=r"(r[1]), "=r"(r[2]), "=r"(r[3]) : "r"(addr));
}

__device__ __forceinline__ uint32_t smem_u32(const void* p) {
  uint32_t a;
  asm("{ .reg .u64 t; cvta.to.shared.u64 t, %1; cvt.u32.u64 %0, t; }"
      : "=r"(a) : "l"(p));
  return a;
}

__device__ __forceinline__ void cp_async16(uint32_t dst, const void* src) {
  asm volatile("cp.async.cg.shared.global [%0], [%1], 16;\n"
               :: "r"(dst), "l"(src) : "memory");
}

// ---------------------------------------------------------------------------
// fp16 tensor-core GEMM: C[M,N] = A[M,Kd] * W[N,Kd]^T (A,W fp16, C fp32)
// 128x128 CTA tile, BK=32, 256 threads (8 warps 2x4), warp tile 64x32,
// m16n8k16 mma + ldmatrix, 2-stage cp.async pipeline.
// smem rows padded to 40 halfs (80B) -> ldmatrix phases conflict-free.
// ---------------------------------------------------------------------------
#define FBM 128
#define FBN 128
#define FBK 32
#define FLD 40   // halfs per row (32 + 8 pad)

__global__ __launch_bounds__(256, 2)
void gemm_f16(const __half* __restrict__ A, const __half* __restrict__ W,
              float* __restrict__ C, int M, int N, int Kd) {
  __shared__ __half As[2][FBM][FLD];
  __shared__ __half Bs[2][FBM][FLD];
  const int bm = blockIdx.y * FBM;
  const int bn = blockIdx.x * FBN;
  const int tid = threadIdx.x;
  const int warp = tid >> 5;
  const int lane = tid & 31;
  const int m0 = (warp >> 2) * 64;
  const int n0 = (warp & 3) * 32;

  const uint32_t sbA = smem_u32(&As[0][0][0]);
  const uint32_t sbB = smem_u32(&Bs[0][0][0]);
  const uint32_t BUFB = FBM * FLD * 2;  // bytes per buffer

  // cp.async map: 512 chunks of 16B per matrix per stage, 2 per thread
  const int e0 = tid, e1 = tid + 256;
  const int r0c = e0 >> 2, c0c = (e0 & 3);   // chunk: 16B = 8 halfs
  const int r1c = e1 >> 2, c1c = (e1 & 3);
  const uint32_t d0 = (uint32_t)(r0c * FLD * 2 + c0c * 16);
  const uint32_t d1 = (uint32_t)(r1c * FLD * 2 + c1c * 16);

  const __half* Ab = A + (size_t)bm * Kd;
  const __half* Wb = W + (size_t)bn * Kd;
  const size_t s0 = (size_t)r0c * Kd + c0c * 8;
  const size_t s1 = (size_t)r1c * Kd + c1c * 8;

#define F16_LOAD(buf, k0)                                                   \
  do {                                                                      \
    cp_async16(sbA + (buf)*BUFB + d0, Ab + s0 + (k0));                      \
    cp_async16(sbA + (buf)*BUFB + d1, Ab + s1 + (k0));                      \
    cp_async16(sbB + (buf)*BUFB + d0, Wb + s0 + (k0));                      \
    cp_async16(sbB + (buf)*BUFB + d1, Wb + s1 + (k0));                      \
    asm volatile("cp.async.commit_group;" ::: "memory");                    \
  } while (0)

  // ldmatrix address components (bytes)
  const uint32_t a_off =
      (uint32_t)(((m0 + (lane & 15)) * FLD + ((lane >> 4) << 3)) * 2);
  const uint32_t b_off =
      (uint32_t)(((n0 + (lane & 7) + ((lane >> 4) & 1) * 8) * FLD +
                  ((lane >> 3) & 1) * 8) * 2);

  float acc[4][4][4];
#pragma unroll
  for (int i = 0; i < 4; i++)
#pragma unroll
    for (int j = 0; j < 4; j++)
#pragma unroll
      for (int q = 0; q < 4; q++) acc[i][j][q] = 0.f;

  const int nk = Kd / FBK;
  F16_LOAD(0, 0);

  for (int t = 0; t < nk; t++) {
    const int buf = t & 1;
    if (t + 1 < nk) {
      F16_LOAD(buf ^ 1, (t + 1) * FBK);
      asm volatile("cp.async.wait_group 1;" ::: "memory");
    } else {
      asm volatile("cp.async.wait_group 0;" ::: "memory");
    }
    __syncthreads();

    const uint32_t aB = sbA + buf * BUFB + a_off;
    const uint32_t bB = sbB + buf * BUFB + b_off;
#pragma unroll
    for (int ks = 0; ks < 2; ks++) {
      const uint32_t ksb = ks * 32;  // 16 halfs
      unsigned a[4][4], b[4][2];
#pragma unroll
      for (int i = 0; i < 4; i++) ldmx4(a[i], aB + i * (16 * FLD * 2) + ksb);
      {
        unsigned t4[4];
        ldmx4(t4, bB + ksb);
        b[0][0] = t4[0]; b[0][1] = t4[1]; b[1][0] = t4[2]; b[1][1] = t4[3];
        ldmx4(t4, bB + 16 * FLD * 2 + ksb);
        b[2][0] = t4[0]; b[2][1] = t4[1]; b[3][0] = t4[2]; b[3][1] = t4[3];
      }
#pragma unroll
      for (int i = 0; i < 4; i++)
#pragma unroll
        for (int j = 0; j < 4; j++) mma_f16(acc[i][j], a[i], b[j]);
    }
    __syncthreads();
  }

  const int g = lane >> 2;
  const int tig = lane & 3;
#pragma unroll
  for (int i = 0; i < 4; i++) {
#pragma unroll
    for (int j = 0; j < 4; j++) {
      const size_t row1 = (size_t)(bm + m0 + i * 16 + g);
      const int col = bn + n0 + j * 8 + tig * 2;
      *(float2*)(C + row1 * N + col) = make_float2(acc[i][j][0], acc[i][j][1]);
      *(float2*)(C + (row1 + 8) * N + col) =
          make_float2(acc[i][j][2], acc[i][j][3]);
    }
  }
}

// ---------------------------------------------------------------------------
// fp32 -> fp16 convert
// ---------------------------------------------------------------------------
__global__ void cvt_f16_kernel(const float* __restrict__ src,
                               __half* __restrict__ dst, int n4) {
  int i = blockIdx.x * blockDim.x + threadIdx.x;
  if (i >= n4) return;
  float4 v = ((const float4*)src)[i];
  __half2 lo = __floats2half2_rn(v.x, v.y);
  __half2 hi = __floats2half2_rn(v.z, v.w);
  ((uint2*)dst)[i] = make_uint2(*(unsigned*)&lo, *(unsigned*)&hi);
}

// ---------------------------------------------------------------------------
// RoPE (fp32 in/out, unchanged)
// ---------------------------------------------------------------------------
__global__ void rope_kernel(float* __restrict__ xp, int nh, int total) {
  int idx = blockIdx.x * blockDim.x + threadIdx.x;
  if (idx >= total) return;
  int i = idx & (HD_ / 2 - 1);
  int t = idx >> 6;
  int h = t % nh;
  int bl = t / nh;
  int pos = bl & (L_ - 1);
  float inv_freq = expf(-(float)i * (2.0f / HD_) * 9.210340371976184f);
  float ang = (float)pos * inv_freq;
  float s, c;
  sincosf(ang, &s, &c);
  size_t base = ((size_t)bl * nh + h) * HD_ + 2 * i;
  float x1 = xp[base], x2 = xp[base + 1];
  xp[base]     = x1 * c - x2 * s;
  xp[base + 1] = x1 * s + x2 * c;
}

// ---------------------------------------------------------------------------
// Tensor-core causal flash attention (tf32 mma, unchanged from round 3)
// except the epilogue writes fp16 (ao feeds the fp16 O-projection GEMM).
// ---------------------------------------------------------------------------
#define AT_TK 32
#define AT_WQ 16
#define AT_WARPS 4
#define AT_QB (AT_WQ * AT_WARPS)   // 64
#define KV_LD 132
#define P_LD 36

__global__ __launch_bounds__(128, 2)
void flash_attn_tc(const float* __restrict__ Q, const float* __restrict__ Kg,
                   const float* __restrict__ Vg, __half* __restrict__ O) {
  __shared__ unsigned Ks[AT_TK][KV_LD];
  __shared__ unsigned Vs[AT_TK][KV_LD];
  __shared__ unsigned Ps[AT_WARPS][AT_WQ][P_LD];

  const int b = blockIdx.z;
  const int h = blockIdx.y;
  const int r0 = blockIdx.x * AT_QB;
  const int kvh = h / REP_;
  const int warp = threadIdx.x >> 5;
  const int lane = threadIdx.x & 31;
  const int g = lane >> 2;
  const int tig = lane & 3;
  const int row0 = r0 + warp * AT_WQ;
  const float scale = 0.088388347648318447f;

  unsigned qa[16][4];
  {
    const float* Qb = Q + ((size_t)(b * L_ + row0) * H_ + h) * HD_;
#pragma unroll
    for (int ks = 0; ks < 16; ks++) {
      const int k0 = ks * 8;
      qa[ks][0] = f2tf32(Qb[(size_t)g * D_ + k0 + tig] * scale);
      qa[ks][1] = f2tf32(Qb[(size_t)(g + 8) * D_ + k0 + tig] * scale);
      qa[ks][2] = f2tf32(Qb[(size_t)g * D_ + k0 + tig + 4] * scale);
      qa[ks][3] = f2tf32(Qb[(size_t)(g + 8) * D_ + k0 + tig + 4] * scale);
    }
  }

  float m0v = -CUDART_INF_F, m1v = -CUDART_INF_F;
  float l0 = 0.f, l1 = 0.f;
  float oa[16][4];
#pragma unroll
  for (int j = 0; j < 16; j++)
#pragma unroll
    for (int q = 0; q < 4; q++) oa[j][q] = 0.f;

  const int tmax = row0 + AT_WQ - 1;
  const int t_end = r0 + AT_QB - 1;

  for (int t0 = 0; t0 <= t_end; t0 += AT_TK) {
#pragma unroll
    for (int i = 0; i < 8; i++) {
      int idx = threadIdx.x + i * 128;
      int row = idx >> 5;
      int c4 = (idx & 31) * 4;
      size_t gp = ((size_t)(b * L_ + t0 + row) * KV_ + kvh) * HD_ + c4;
      float4 k4 = *(const float4*)(Kg + gp);
      *(uint4*)&Ks[row][c4] =
          make_uint4(f2tf32(k4.x), f2tf32(k4.y), f2tf32(k4.z), f2tf32(k4.w));
      float4 v4 = *(const float4*)(Vg + gp);
      *(uint4*)&Vs[row][c4] =
          make_uint4(f2tf32(v4.x), f2tf32(v4.y), f2tf32(v4.z), f2tf32(v4.w));
    }
    __syncthreads();

    if (t0 <= tmax) {
      float sf[4][4];
#pragma unroll
      for (int j = 0; j < 4; j++)
#pragma unroll
        for (int q = 0; q < 4; q++) sf[j][q] = 0.f;

#pragma unroll
      for (int ks = 0; ks < 16; ks++) {
        const int kb = ks * 8;
        unsigned bk[4][2];
#pragma unroll
        for (int j = 0; j < 4; j++) {
          bk[j][0] = Ks[j * 8 + g][kb + tig];
          bk[j][1] = Ks[j * 8 + g][kb + tig + 4];
        }
#pragma unroll
        for (int j = 0; j < 4; j++) mma_tf32(sf[j], qa[ks], bk[j]);
      }

      if (t0 + AT_TK - 1 > row0) {
#pragma unroll
        for (int j = 0; j < 4; j++) {
          const int col = t0 + j * 8 + 2 * tig;
          if (col > row0 + g) sf[j][0] = -CUDART_INF_F;
          if (col + 1 > row0 + g) sf[j][1] = -CUDART_INF_F;
          if (col > row0 + g + 8) sf[j][2] = -CUDART_INF_F;
          if (col + 1 > row0 + g + 8) sf[j][3] = -CUDART_INF_F;
        }
      }

      float tm0 = sf[0][0], tm1 = sf[0][2];
#pragma unroll
      for (int j = 0; j < 4; j++) {
        tm0 = fmaxf(tm0, fmaxf(sf[j][0], sf[j][1]));
        tm1 = fmaxf(tm1, fmaxf(sf[j][2], sf[j][3]));
      }
      tm0 = fmaxf(tm0, __shfl_xor_sync(0xffffffffu, tm0, 1));
      tm0 = fmaxf(tm0, __shfl_xor_sync(0xffffffffu, tm0, 2));
      tm1 = fmaxf(tm1, __shfl_xor_sync(0xffffffffu, tm1, 1));
      tm1 = fmaxf(tm1, __shfl_xor_sync(0xffffffffu, tm1, 2));

      const float mn0 = fmaxf(m0v, tm0);
      const float mn1 = fmaxf(m1v, tm1);
      const float cr0 = __expf(m0v - mn0);
      const float cr1 = __expf(m1v - mn1);

      float ps0 = 0.f, ps1 = 0.f;
#pragma unroll
      for (int j = 0; j < 4; j++) {
        sf[j][0] = __expf(sf[j][0] - mn0);
        sf[j][1] = __expf(sf[j][1] - mn0);
        sf[j][2] = __expf(sf[j][2] - mn1);
        sf[j][3] = __expf(sf[j][3] - mn1);
        ps0 += sf[j][0] + sf[j][1];
        ps1 += sf[j][2] + sf[j][3];
      }
      ps0 += __shfl_xor_sync(0xffffffffu, ps0, 1);
      ps0 += __shfl_xor_sync(0xffffffffu, ps0, 2);
      ps1 += __shfl_xor_sync(0xffffffffu, ps1, 1);
      ps1 += __shfl_xor_sync(0xffffffffu, ps1, 2);

      l0 = l0 * cr0 + ps0;
      l1 = l1 * cr1 + ps1;
      m0v = mn0;
      m1v = mn1;

#pragma unroll
      for (int j2 = 0; j2 < 16; j2++) {
        oa[j2][0] *= cr0; oa[j2][1] *= cr0;
        oa[j2][2] *= cr1; oa[j2][3] *= cr1;
      }

#pragma unroll
      for (int j = 0; j < 4; j++) {
        *(uint2*)&Ps[warp][g][j * 8 + 2 * tig] =
            make_uint2(f2tf32(sf[j][0]), f2tf32(sf[j][1]));
        *(uint2*)&Ps[warp][g + 8][j * 8 + 2 * tig] =
            make_uint2(f2tf32(sf[j][2]), f2tf32(sf[j][3]));
      }
      __syncwarp();

#pragma unroll
      for (int kb4 = 0; kb4 < 4; kb4++) {
        const int kb = kb4 * 8;
        unsigned pa[4];
        pa[0] = Ps[warp][g][kb + tig];
        pa[1] = Ps[warp][g + 8][kb + tig];
        pa[2] = Ps[warp][g][kb + tig + 4];
        pa[3] = Ps[warp][g + 8][kb + tig + 4];
#pragma unroll
        for (int j2 = 0; j2 < 16; j2++) {
          unsigned bv[2];
          bv[0] = Vs[kb + tig][j2 * 8 + g];
          bv[1] = Vs[kb + tig + 4][j2 * 8 + g];
          mma_tf32(oa[j2], pa, bv);
        }
      }
    }
    __syncthreads();
  }

  const float inv0 = 1.0f / l0;
  const float inv1 = 1.0f / l1;
  __half* Ob = O + ((size_t)(b * L_ + row0) * H_ + h) * HD_;
#pragma unroll
  for (int j2 = 0; j2 < 16; j2++) {
    const int col = j2 * 8 + 2 * tig;
    __half2 h0 = __floats2half2_rn(oa[j2][0] * inv0, oa[j2][1] * inv0);
    __half2 h1 = __floats2half2_rn(oa[j2][2] * inv1, oa[j2][3] * inv1);
    *(__half2*)(Ob + (size_t)g * D_ + col) = h0;
    *(__half2*)(Ob + (size_t)(g + 8) * D_ + col) = h1;
  }
}

// ---------------------------------------------------------------------------
extern "C" void kernel_launch(void* const* d_in, const int* in_sizes, int n_in,
                              void* d_out, int out_size) {
  (void)in_sizes; (void)n_in; (void)out_size;
  const float* x  = (const float*)d_in[0];
  const float* wq = (const float*)d_in[1];
  const float* wk = (const float*)d_in[2];
  const float* wv = (const float*)d_in[3];
  const float* wo = (const float*)d_in[4];
  float* out = (float*)d_out;

  float *q, *k, *v;
  __half *xh, *wqh, *wkh, *wvh, *woh, *aoh;
  cudaGetSymbolAddress((void**)&q, g_q);
  cudaGetSymbolAddress((void**)&k, g_k);
  cudaGetSymbolAddress((void**)&v, g_v);
  cudaGetSymbolAddress((void**)&xh, g_xh);
  cudaGetSymbolAddress((void**)&wqh, g_wqh);
  cudaGetSymbolAddress((void**)&wkh, g_wkh);
  cudaGetSymbolAddress((void**)&wvh, g_wvh);
  cudaGetSymbolAddress((void**)&woh, g_woh);
  cudaGetSymbolAddress((void**)&aoh, g_aoh);

  const int M = B_ * L_;  // 4096

  // fp16 conversion of GEMM operands
  {
    int n4;
    n4 = (B_ * L_ * D_) / 4;
    cvt_f16_kernel<<<(n4 + 255) / 256, 256>>>(x, xh, n4);
    n4 = (D_ * D_) / 4;
    cvt_f16_kernel<<<(n4 + 255) / 256, 256>>>(wq, wqh, n4);
    cvt_f16_kernel<<<(n4 + 255) / 256, 256>>>(wo, woh, n4);
    n4 = (KV_ * HD_ * D_) / 4;
    cvt_f16_kernel<<<(n4 + 255) / 256, 256>>>(wk, wkh, n4);
    cvt_f16_kernel<<<(n4 + 255) / 256, 256>>>(wv, wvh, n4);
  }

  // Q/K/V projections (fp16 mma + ldmatrix)
  gemm_f16<<<dim3(D_ / FBN, M / FBM), 256>>>(xh, wqh, q, M, D_, D_);
  gemm_f16<<<dim3((KV_ * HD_) / FBN, M / FBM), 256>>>(xh, wkh, k, M,
                                                      KV_ * HD_, D_);
  gemm_f16<<<dim3((KV_ * HD_) / FBN, M / FBM), 256>>>(xh, wvh, v, M,
                                                      KV_ * HD_, D_);

  // RoPE on q and k
  int nq = B_ * L_ * H_ * (HD_ / 2);
  rope_kernel<<<nq / 256, 256>>>(q, H_, nq);
  int nk = B_ * L_ * KV_ * (HD_ / 2);
  rope_kernel<<<nk / 256, 256>>>(k, KV_, nk);

  // causal attention (tensor cores), fp16 output for O-projection
  flash_attn_tc<<<dim3(L_ / AT_QB, H_, B_), 128>>>(q, k, v, aoh);

  // output projection -> d_out
  gemm_f16<<<dim3(D_ / FBN, M / FBM), 256>>>(aoh, woh, out, M, D_, D_);
}